// round 16
// baseline (speedup 1.0000x reference)
#include <cuda_runtime.h>
#include <cuda_fp16.h>
#include <math.h>
#include <stdint.h>

#define PB 4
#define PS 4096
#define PD 1024
#define NM (PB * PS)
#define NCTA 296          // 2 CTAs x 148 SMs, persistent

typedef __half f16;

// ---------------------------------------------------------------------------
// Scratch planes (device globals — allocation-free per harness rules)
// ---------------------------------------------------------------------------
__device__ f16 g_x[(size_t)NM * PD];
__device__ f16 g_Wt[3 * (size_t)PD * PD];     // W^T [3][n][k]
__device__ f16 g_Q[(size_t)NM * PD];
__device__ f16 g_K[(size_t)NM * PD];
__device__ f16 g_V[(size_t)NM * PD];
__device__ f16 g_P[(size_t)PB * PS * PS];     // unnormalized exp(s/32 - 5), masked=0
__device__ float g_psum[64][NM];              // per-(64-col half) row partial sums

// ---------------------------------------------------------------------------
// Baseline-PTX helpers (no 'a'-suffix features)
// ---------------------------------------------------------------------------
__device__ __forceinline__ uint32_t smem_u32(const void* p) {
    uint32_t a;
    asm("{ .reg .u64 t; cvta.to.shared.u64 t, %1; cvt.u32.u64 %0, t; }"
        : "=r"(a) : "l"(p));
    return a;
}

__device__ __forceinline__ void cpa16(uint32_t s, const void* g) {
    asm volatile("cp.async.cg.shared.global [%0], [%1], 16;\n" :: "r"(s), "l"(g));
}
__device__ __forceinline__ void cpa_commit() {
    asm volatile("cp.async.commit_group;\n");
}
__device__ __forceinline__ void cpa_wait0() { asm volatile("cp.async.wait_group 0;\n"); }
__device__ __forceinline__ void cpa_wait1() { asm volatile("cp.async.wait_group 1;\n"); }

__device__ __forceinline__ void ldsm4(uint32_t* r, uint32_t a) {
    asm volatile("ldmatrix.sync.aligned.m8n8.x4.shared.b16 {%0,%1,%2,%3}, [%4];\n"
                 : "=r"(r[0]), "=r"(r[1]), "=r"(r[2]), "=r"(r[3]) : "r"(a));
}
__device__ __forceinline__ void ldsm4t(uint32_t* r, uint32_t a) {
    asm volatile("ldmatrix.sync.aligned.m8n8.x4.trans.shared.b16 {%0,%1,%2,%3}, [%4];\n"
                 : "=r"(r[0]), "=r"(r[1]), "=r"(r[2]), "=r"(r[3]) : "r"(a));
}
__device__ __forceinline__ void mma16816(float* c, const uint32_t* a, const uint32_t* b) {
    asm volatile(
        "mma.sync.aligned.m16n8k16.row.col.f32.f16.f16.f32 "
        "{%0,%1,%2,%3}, {%4,%5,%6,%7}, {%8,%9}, {%0,%1,%2,%3};\n"
        : "+f"(c[0]), "+f"(c[1]), "+f"(c[2]), "+f"(c[3])
        : "r"(a[0]), "r"(a[1]), "r"(a[2]), "r"(a[3]), "r"(b[0]), "r"(b[1]));
}

// Stage layout (bytes). CTA tile 128m x 128n, K-chunk 64.
//   A plane at 0: 128 rows x 128B data, 144B stride = 18432B
//   B plane at 18432:
//     k-major: 128 rows x 128B data, 144B stride = 18432B
//     trans:   64 k-rows x 256B data, 272B stride = 17408B
#define OB 18432
#define STG 36864
#define NSTAGE 3

// ---------------------------------------------------------------------------
// Stage loader: K-chunk 64 via cp.async (16B chunks).
// ---------------------------------------------------------------------------
template <bool BT>
__device__ __forceinline__ void load_stage(
    uint32_t sb, const f16* __restrict__ A, size_t ap,
    const f16* __restrict__ B, size_t bp, int ch, int tid)
{
    const int k0 = ch << 6;
#pragma unroll
    for (int t = 0; t < 4; t++) {
        const int idx = tid + (t << 8);
        const int row = idx >> 3, seg = idx & 7;        // 128 rows x 8 segs
        cpa16(sb + row * 144 + (seg << 4), A + (size_t)row * ap + k0 + (seg << 3));
    }
    if (!BT) {
#pragma unroll
        for (int t = 0; t < 4; t++) {
            const int idx = tid + (t << 8);
            const int row = idx >> 3, seg = idx & 7;
            cpa16(sb + OB + row * 144 + (seg << 4),
                  B + (size_t)row * bp + k0 + (seg << 3));
        }
    } else {
#pragma unroll
        for (int t = 0; t < 4; t++) {
            const int idx = tid + (t << 8);
            const int row = idx >> 4, seg = idx & 15;   // 64 k-rows x 16 segs
            cpa16(sb + OB + row * 272 + (seg << 4),
                  B + (size_t)(k0 + row) * bp + (seg << 3));
        }
    }
    cpa_commit();
}

// ---------------------------------------------------------------------------
// Compute one K-chunk (four k16 steps). Warp tile m32 x n64. acc += A.B
// ---------------------------------------------------------------------------
template <bool BT>
__device__ __forceinline__ void compute_chunk(
    float acc[2][8][4], uint32_t sb, int lane, int wm, int wn)
{
#pragma unroll
    for (int kk = 0; kk < 4; kk++) {
        const uint32_t kbyte = kk << 5;
        uint32_t a_r[2][4];
#pragma unroll
        for (int mt = 0; mt < 2; mt++) {
            ldsm4(a_r[mt], sb + (wm + (mt << 4) + (lane & 15)) * 144
                         + kbyte + ((lane >> 4) << 4));
        }
        const int g = lane >> 3;
#pragma unroll
        for (int p = 0; p < 4; p++) {
            uint32_t addr;
            if (!BT) {
                addr = sb + OB + (wn + (((p << 1) + (g >> 1)) << 3) + (lane & 7)) * 144
                     + kbyte + ((g & 1) << 4);
            } else {
                addr = sb + OB + ((kk << 4) + ((g & 1) << 3) + (lane & 7)) * 272
                     + ((wn + (((p << 1) + (g >> 1)) << 3)) << 1);
            }
            uint32_t r[4];
            if (!BT) ldsm4(r, addr); else ldsm4t(r, addr);
            uint32_t b0[2] = {r[0], r[1]};
            uint32_t b1[2] = {r[2], r[3]};
#pragma unroll
            for (int mt = 0; mt < 2; mt++) {
                mma16816(acc[mt][p * 2],     a_r[mt], b0);
                mma16816(acc[mt][p * 2 + 1], a_r[mt], b1);
            }
        }
    }
}

__device__ __forceinline__ uint32_t pack2h(float v0, float v1) {
    __half2 t = __halves2half2(__float2half(v0), __float2half(v1));
    return *reinterpret_cast<uint32_t*>(&t);
}

__device__ __forceinline__ void zero_acc(float acc[2][8][4]) {
#pragma unroll
    for (int a = 0; a < 2; a++)
#pragma unroll
        for (int b = 0; b < 8; b++)
#pragma unroll
            for (int c = 0; c < 4; c++) acc[a][b][c] = 0.f;
}

// Shared fp16 projection epilogue (write acc tile to Y at (m0, n0)).
__device__ __forceinline__ void proj_epilogue(
    float acc[2][8][4], f16* Y, int m0, int n0)
{
    const int lane = threadIdx.x & 31, wid = threadIdx.x >> 5;
    const int wm = (wid & 3) << 5, wn = (wid >> 2) << 6;
#pragma unroll
    for (int mt = 0; mt < 2; mt++)
#pragma unroll
        for (int nt = 0; nt < 8; nt++) {
            const int col = n0 + wn + (nt << 3) + ((lane & 3) << 1);
#pragma unroll
            for (int h = 0; h < 2; h++) {
                const int row = m0 + wm + (mt << 4) + (lane >> 2) + (h << 3);
                *(uint32_t*)(Y + (size_t)row * PD + col) =
                    pack2h(acc[mt][nt][2 * h], acc[mt][nt][2 * h + 1]);
            }
        }
}

// ---------------------------------------------------------------------------
// x -> fp16 plane
// ---------------------------------------------------------------------------
__global__ __launch_bounds__(256) void convx_kernel(const float* __restrict__ x) {
    size_t i = ((size_t)blockIdx.x * 256 + threadIdx.x) * 4;
    float4 v = *(const float4*)(x + i);
    *(uint2*)(g_x + i) = make_uint2(pack2h(v.x, v.y), pack2h(v.z, v.w));
}

// ---------------------------------------------------------------------------
// W -> W^T fp16 plane
// ---------------------------------------------------------------------------
__global__ __launch_bounds__(256) void convw_kernel(const float* __restrict__ Wq,
                                                    const float* __restrict__ Wk,
                                                    const float* __restrict__ Wv) {
    __shared__ float t[32][33];
    const float* W = blockIdx.z == 0 ? Wq : blockIdx.z == 1 ? Wk : Wv;
    const int n0 = blockIdx.x * 32, k0 = blockIdx.y * 32;
    const int tx = threadIdx.x & 31, ty = threadIdx.x >> 5;
    for (int i = ty; i < 32; i += 8)
        t[i][tx] = W[(size_t)(k0 + i) * PD + n0 + tx];
    __syncthreads();
    const size_t base = (size_t)blockIdx.z << 20;
    for (int i = ty; i < 32; i += 8)
        g_Wt[base + (size_t)(n0 + i) * PD + k0 + tx] = __float2half(t[tx][i]);
}

extern __shared__ char dynsm[];

// ---------------------------------------------------------------------------
// Persistent Q,K projection. 2048 uniform tiles (16 chunks each); continuous
// cross-tile cp.async stream so the ring never drains at tile boundaries.
// ---------------------------------------------------------------------------
__global__ __launch_bounds__(256, 2) void proj_mma_kernel() {
    const int tid = threadIdx.x;
    const int lane = tid & 31, wid = tid >> 5;
    const int wm = (wid & 3) << 5, wn = (wid >> 2) << 6;
    const uint32_t sb = smem_u32(dynsm);
    const int NT = 2048;

    int t_load = blockIdx.x, c_load = 0;
    const f16 *Al = nullptr, *Bl = nullptr;
    if (t_load < NT) {
        Al = g_x + (((size_t)((t_load & 1023) >> 3)) << 7) * PD;
        Bl = g_Wt + ((size_t)(t_load >> 10) << 20)
           + (((size_t)(t_load & 7)) << 7) * PD;
    }
    int t_comp = blockIdx.x, c_comp = 0;
    int inflight = 0, s_load = 0, s_comp = 0;

#pragma unroll 1
    for (int k = 0; k < 2 && t_load < NT; k++) {
        load_stage<false>(sb + s_load * STG, Al, PD, Bl, PD, c_load, tid);
        s_load = (s_load == 2) ? 0 : s_load + 1; inflight++;
        if (++c_load == 16) {
            c_load = 0; t_load += NCTA;
            if (t_load < NT) {
                Al = g_x + (((size_t)((t_load & 1023) >> 3)) << 7) * PD;
                Bl = g_Wt + ((size_t)(t_load >> 10) << 20)
                   + (((size_t)(t_load & 7)) << 7) * PD;
            }
        }
    }

    float acc[2][8][4];
    zero_acc(acc);
#pragma unroll 1
    while (t_comp < NT) {
        if (inflight > 1) cpa_wait1(); else cpa_wait0();
        __syncthreads();
        if (t_load < NT) {
            load_stage<false>(sb + s_load * STG, Al, PD, Bl, PD, c_load, tid);
            s_load = (s_load == 2) ? 0 : s_load + 1; inflight++;
            if (++c_load == 16) {
                c_load = 0; t_load += NCTA;
                if (t_load < NT) {
                    Al = g_x + (((size_t)((t_load & 1023) >> 3)) << 7) * PD;
                    Bl = g_Wt + ((size_t)(t_load >> 10) << 20)
                       + (((size_t)(t_load & 7)) << 7) * PD;
                }
            }
        }
        compute_chunk<false>(acc, sb + s_comp * STG, lane, wm, wn);
        s_comp = (s_comp == 2) ? 0 : s_comp + 1; inflight--;
        if (++c_comp == 16) {
            c_comp = 0;
            proj_epilogue(acc, (t_comp >> 10) ? g_K : g_Q,
                          ((t_comp & 1023) >> 3) << 7, (t_comp & 7) << 7);
            zero_acc(acc);
            t_comp += NCTA;
        }
    }
}

// ---------------------------------------------------------------------------
// Scores tile decode: t < 2112 -> causal (b, qt, kt via triangular decode);
// else V-projection tile. All tiles 16 chunks (uniform).
// ---------------------------------------------------------------------------
__device__ __forceinline__ void scores_decode(int t, const f16*& A, const f16*& B) {
    if (t < 2112) {
        const int b = t / 528, r = t - b * 528;
        int qt = (int)((sqrtf(8.f * r + 1.f) - 1.f) * 0.5f);
        while ((qt + 1) * (qt + 2) / 2 <= r) qt++;
        while (qt * (qt + 1) / 2 > r) qt--;
        const int kt = r - qt * (qt + 1) / 2;
        A = g_Q + (size_t)(b * PS + (qt << 7)) * PD;
        B = g_K + (size_t)(b * PS + (kt << 7)) * PD;
    } else {
        const int idx = t - 2112;
        A = g_x + (((size_t)(idx >> 3)) << 7) * PD;
        B = g_Wt + ((size_t)2 << 20) + (((size_t)(idx & 7)) << 7) * PD;
    }
}

// ---------------------------------------------------------------------------
// Persistent scores + V-projection. 3136 uniform tiles.
// ---------------------------------------------------------------------------
__global__ __launch_bounds__(256, 2) void scores_mma_kernel() {
    const int tid = threadIdx.x;
    const int lane = tid & 31, wid = tid >> 5;
    const int wm = (wid & 3) << 5, wn = (wid >> 2) << 6;
    const uint32_t sb = smem_u32(dynsm);
    const int NT = 2112 + 1024;

    int t_load = blockIdx.x, c_load = 0;
    const f16 *Al = nullptr, *Bl = nullptr;
    if (t_load < NT) scores_decode(t_load, Al, Bl);
    int t_comp = blockIdx.x, c_comp = 0;
    int inflight = 0, s_load = 0, s_comp = 0;

#pragma unroll 1
    for (int k = 0; k < 2 && t_load < NT; k++) {
        load_stage<false>(sb + s_load * STG, Al, PD, Bl, PD, c_load, tid);
        s_load = (s_load == 2) ? 0 : s_load + 1; inflight++;
        if (++c_load == 16) {
            c_load = 0; t_load += NCTA;
            if (t_load < NT) scores_decode(t_load, Al, Bl);
        }
    }

    float acc[2][8][4];
    zero_acc(acc);
#pragma unroll 1
    while (t_comp < NT) {
        if (inflight > 1) cpa_wait1(); else cpa_wait0();
        __syncthreads();
        if (t_load < NT) {
            load_stage<false>(sb + s_load * STG, Al, PD, Bl, PD, c_load, tid);
            s_load = (s_load == 2) ? 0 : s_load + 1; inflight++;
            if (++c_load == 16) {
                c_load = 0; t_load += NCTA;
                if (t_load < NT) scores_decode(t_load, Al, Bl);
            }
        }
        compute_chunk<false>(acc, sb + s_comp * STG, lane, wm, wn);
        s_comp = (s_comp == 2) ? 0 : s_comp + 1; inflight--;
        if (++c_comp == 16) {
            c_comp = 0;
            // ---- epilogue for tile t_comp ----
            if (t_comp < 2112) {
                const int b = t_comp / 528, r = t_comp - b * 528;
                int qt = (int)((sqrtf(8.f * r + 1.f) - 1.f) * 0.5f);
                while ((qt + 1) * (qt + 2) / 2 <= r) qt++;
                while (qt * (qt + 1) / 2 > r) qt--;
                const int kt = r - qt * (qt + 1) / 2;
                const int q0 = qt << 7, k0 = kt << 7;
                f16* Pb = g_P + (size_t)b * PS * PS;
                float rsum[2][2] = {};
#pragma unroll
                for (int mt = 0; mt < 2; mt++)
#pragma unroll
                    for (int nt = 0; nt < 8; nt++) {
                        const int k = k0 + wn + (nt << 3) + ((lane & 3) << 1);
#pragma unroll
                        for (int h = 0; h < 2; h++) {
                            const int q = q0 + wm + (mt << 4) + (lane >> 2) + (h << 3);
                            const float p0 = (k > q) ? 0.f
                                : __expf(acc[mt][nt][2 * h] * 0.03125f - 5.0f);
                            const float p1 = (k + 1 > q) ? 0.f
                                : __expf(acc[mt][nt][2 * h + 1] * 0.03125f - 5.0f);
                            *(uint32_t*)(Pb + (size_t)q * PS + k) = pack2h(p0, p1);
                            rsum[mt][h] += p0 + p1;
                        }
                    }
#pragma unroll
                for (int mt = 0; mt < 2; mt++)
#pragma unroll
                    for (int h = 0; h < 2; h++) {
                        float s = rsum[mt][h];
                        s += __shfl_xor_sync(0xffffffffu, s, 1);
                        s += __shfl_xor_sync(0xffffffffu, s, 2);
                        if ((lane & 3) == 0) {
                            const int q = q0 + wm + (mt << 4) + (lane >> 2) + (h << 3);
                            g_psum[(kt << 1) + (wn >> 6)][b * PS + q] = s;
                        }
                    }
            } else {
                const int idx = t_comp - 2112;
                proj_epilogue(acc, g_V, (idx >> 3) << 7, (idx & 7) << 7);
            }
            zero_acc(acc);
            t_comp += NCTA;
        }
    }
}

// ---------------------------------------------------------------------------
// Persistent PV. 1024 tiles, variable chunks (qt+1)*2; qt round-robin in the
// tile id balances per-CTA totals. s_inv lives after the ring in dyn smem.
// ---------------------------------------------------------------------------
__device__ __forceinline__ void pv_decode(int t, const f16*& A, const f16*& B,
                                          int& qt, int& b, int& n0) {
    qt = t & 31;
    const int rest = t >> 5;
    b = rest & 3;
    n0 = (rest >> 2) << 7;
    A = g_P + (size_t)b * PS * PS + ((size_t)qt << 7) * PS;
    B = g_V + (size_t)(b * PS) * PD + n0;
}

__global__ __launch_bounds__(256, 2) void pv_mma_kernel(float* __restrict__ Out) {
    const int tid = threadIdx.x;
    const int lane = tid & 31, wid = tid >> 5;
    const int wm = (wid & 3) << 5, wn = (wid >> 2) << 6;
    const uint32_t sb = smem_u32(dynsm);
    float* s_inv = (float*)(dynsm + NSTAGE * STG);
    const int NT = 1024;

    int t_load = blockIdx.x, c_load = 0, nch_l = 0;
    const f16 *Al = nullptr, *Bl = nullptr;
    if (t_load < NT) {
        int qt, b, n0;
        pv_decode(t_load, Al, Bl, qt, b, n0);
        nch_l = (qt + 1) << 1;
    }
    int t_comp = blockIdx.x, c_comp = 0, nch_c = nch_l;
    int inflight = 0, s_load = 0, s_comp = 0;

#pragma unroll 1
    for (int k = 0; k < 2 && t_load < NT; k++) {
        load_stage<true>(sb + s_load * STG, Al, PS, Bl, PD, c_load, tid);
        s_load = (s_load == 2) ? 0 : s_load + 1; inflight++;
        if (++c_load == nch_l) {
            c_load = 0; t_load += NCTA;
            if (t_load < NT) {
                int qt, b, n0;
                pv_decode(t_load, Al, Bl, qt, b, n0);
                nch_l = (qt + 1) << 1;
            }
        }
    }

    float acc[2][8][4];
    zero_acc(acc);
#pragma unroll 1
    while (t_comp < NT) {
        if (inflight > 1) cpa_wait1(); else cpa_wait0();
        __syncthreads();
        if (t_load < NT) {
            load_stage<true>(sb + s_load * STG, Al, PS, Bl, PD, c_load, tid);
            s_load = (s_load == 2) ? 0 : s_load + 1; inflight++;
            if (++c_load == nch_l) {
                c_load = 0; t_load += NCTA;
                if (t_load < NT) {
                    int qt, b, n0;
                    pv_decode(t_load, Al, Bl, qt, b, n0);
                    nch_l = (qt + 1) << 1;
                }
            }
        }
        compute_chunk<true>(acc, sb + s_comp * STG, lane, wm, wn);
        s_comp = (s_comp == 2) ? 0 : s_comp + 1; inflight--;
        if (++c_comp == nch_c) {
            c_comp = 0;
            // ---- epilogue for tile t_comp ----
            const int qt = t_comp & 31;
            const int rest = t_comp >> 5;
            const int b = rest & 3;
            const int n0 = (rest >> 2) << 7;
            const int q0 = qt << 7;
            if (tid < 128) {
                const int row = b * PS + q0 + tid;
                const int nh = (qt + 1) << 1;
                float s = 0.f;
                for (int i = 0; i < nh; i++) s += g_psum[i][row];
                s_inv[tid] = 1.0f / s;
            }
            __syncthreads();
            float inv[2][2];
#pragma unroll
            for (int mt = 0; mt < 2; mt++)
#pragma unroll
                for (int h = 0; h < 2; h++)
                    inv[mt][h] = s_inv[wm + (mt << 4) + (lane >> 2) + (h << 3)];
#pragma unroll
            for (int mt = 0; mt < 2; mt++)
#pragma unroll
                for (int nt = 0; nt < 8; nt++) {
                    const int col = n0 + wn + (nt << 3) + ((lane & 3) << 1);
#pragma unroll
                    for (int h = 0; h < 2; h++) {
                        const int row = q0 + wm + (mt << 4) + (lane >> 2) + (h << 3);
                        *(float2*)(Out + ((size_t)b * PS + row) * PD + col) =
                            make_float2(acc[mt][nt][2 * h] * inv[mt][h],
                                        acc[mt][nt][2 * h + 1] * inv[mt][h]);
                    }
                }
            zero_acc(acc);
            t_comp += NCTA;
            nch_c = ((t_comp & 31) + 1) << 1;
        }
    }
}

// ---------------------------------------------------------------------------
extern "C" void kernel_launch(void* const* d_in, const int* in_sizes, int n_in,
                              void* d_out, int out_size) {
    (void)in_sizes; (void)n_in; (void)out_size;
    const float* x  = (const float*)d_in[0];
    const float* Wq = (const float*)d_in[1];
    const float* Wk = (const float*)d_in[2];
    const float* Wv = (const float*)d_in[3];
    float* out = (float*)d_out;

    const int smem  = NSTAGE * STG;          // 110592 B
    const int smemp = NSTAGE * STG + 512;    // + s_inv for PV
    cudaFuncSetAttribute(proj_mma_kernel,   cudaFuncAttributeMaxDynamicSharedMemorySize, smem);
    cudaFuncSetAttribute(scores_mma_kernel, cudaFuncAttributeMaxDynamicSharedMemorySize, smem);
    cudaFuncSetAttribute(pv_mma_kernel,     cudaFuncAttributeMaxDynamicSharedMemorySize, smemp);

    convx_kernel<<<16384, 256>>>(x);
    convw_kernel<<<dim3(32, 32, 3), 256>>>(Wq, Wk, Wv);

    proj_mma_kernel<<<NCTA, 256, smem>>>();        // Q, K (persistent)

    scores_mma_kernel<<<NCTA, 256, smem>>>();      // scores + V-proj (persistent)

    pv_mma_kernel<<<NCTA, 256, smemp>>>(out);      // PV + rsum fold (persistent)
}

// round 17
// speedup vs baseline: 1.1326x; 1.1326x over previous
#include <cuda_runtime.h>
#include <cuda_fp16.h>
#include <math.h>
#include <stdint.h>

#define PB 4
#define PS 4096
#define PD 1024
#define NM (PB * PS)

typedef __half f16;

// ---------------------------------------------------------------------------
// Scratch planes (device globals — allocation-free per harness rules)
// ---------------------------------------------------------------------------
__device__ f16 g_x[(size_t)NM * PD];
__device__ f16 g_Wt[3 * (size_t)PD * PD];     // W^T [3][n][k]
__device__ f16 g_Q[(size_t)NM * PD];
__device__ f16 g_K[(size_t)NM * PD];
__device__ f16 g_V[(size_t)NM * PD];
__device__ f16 g_P[(size_t)PB * PS * PS];     // unnormalized exp(s/32 - 5), masked=0
__device__ float g_psum[64][NM];              // per-(64-col half) row partial sums

// ---------------------------------------------------------------------------
// Baseline-PTX helpers (no 'a'-suffix features)
// ---------------------------------------------------------------------------
__device__ __forceinline__ uint32_t smem_u32(const void* p) {
    uint32_t a;
    asm("{ .reg .u64 t; cvta.to.shared.u64 t, %1; cvt.u32.u64 %0, t; }"
        : "=r"(a) : "l"(p));
    return a;
}

__device__ __forceinline__ void cpa16(uint32_t s, const void* g) {
    asm volatile("cp.async.cg.shared.global [%0], [%1], 16;\n" :: "r"(s), "l"(g));
}
__device__ __forceinline__ void cpa_commit() {
    asm volatile("cp.async.commit_group;\n");
}
__device__ __forceinline__ void cpa_wait0() { asm volatile("cp.async.wait_group 0;\n"); }
__device__ __forceinline__ void cpa_wait1() { asm volatile("cp.async.wait_group 1;\n"); }

__device__ __forceinline__ void ldsm4(uint32_t* r, uint32_t a) {
    asm volatile("ldmatrix.sync.aligned.m8n8.x4.shared.b16 {%0,%1,%2,%3}, [%4];\n"
                 : "=r"(r[0]), "=r"(r[1]), "=r"(r[2]), "=r"(r[3]) : "r"(a));
}
__device__ __forceinline__ void ldsm4t(uint32_t* r, uint32_t a) {
    asm volatile("ldmatrix.sync.aligned.m8n8.x4.trans.shared.b16 {%0,%1,%2,%3}, [%4];\n"
                 : "=r"(r[0]), "=r"(r[1]), "=r"(r[2]), "=r"(r[3]) : "r"(a));
}
__device__ __forceinline__ void mma16816(float* c, const uint32_t* a, const uint32_t* b) {
    asm volatile(
        "mma.sync.aligned.m16n8k16.row.col.f32.f16.f16.f32 "
        "{%0,%1,%2,%3}, {%4,%5,%6,%7}, {%8,%9}, {%0,%1,%2,%3};\n"
        : "+f"(c[0]), "+f"(c[1]), "+f"(c[2]), "+f"(c[3])
        : "r"(a[0]), "r"(a[1]), "r"(a[2]), "r"(a[3]), "r"(b[0]), "r"(b[1]));
}

// Stage layout (bytes). CTA tile 128m x 128n, K-chunk 64.
//   A plane at 0: 128 rows x 128B data, 144B stride = 18432B
//   B plane at 18432:
//     k-major: 128 rows x 128B data, 144B stride = 18432B
//     trans:   64 k-rows x 256B data, 272B stride = 17408B
#define OB 18432
#define STG 36864
#define NSTAGE 3

// ---------------------------------------------------------------------------
// Stage loader: K-chunk 64 via cp.async (16B chunks).
// ---------------------------------------------------------------------------
template <bool BT>
__device__ __forceinline__ void load_stage(
    uint32_t sb, const f16* __restrict__ A, size_t ap,
    const f16* __restrict__ B, size_t bp, int ch, int tid)
{
    const int k0 = ch << 6;
#pragma unroll
    for (int t = 0; t < 4; t++) {
        const int idx = tid + (t << 8);
        const int row = idx >> 3, seg = idx & 7;        // 128 rows x 8 segs
        cpa16(sb + row * 144 + (seg << 4), A + (size_t)row * ap + k0 + (seg << 3));
    }
    if (!BT) {
#pragma unroll
        for (int t = 0; t < 4; t++) {
            const int idx = tid + (t << 8);
            const int row = idx >> 3, seg = idx & 7;
            cpa16(sb + OB + row * 144 + (seg << 4),
                  B + (size_t)row * bp + k0 + (seg << 3));
        }
    } else {
#pragma unroll
        for (int t = 0; t < 4; t++) {
            const int idx = tid + (t << 8);
            const int row = idx >> 4, seg = idx & 15;   // 64 k-rows x 16 segs
            cpa16(sb + OB + row * 272 + (seg << 4),
                  B + (size_t)(k0 + row) * bp + (seg << 3));
        }
    }
    cpa_commit();
}

// ---------------------------------------------------------------------------
// Compute one K-chunk (four k16 steps). Warp tile m32 x n64. acc += A.B
// ---------------------------------------------------------------------------
template <bool BT>
__device__ __forceinline__ void compute_chunk(
    float acc[2][8][4], uint32_t sb, int lane, int wm, int wn)
{
#pragma unroll
    for (int kk = 0; kk < 4; kk++) {
        const uint32_t kbyte = kk << 5;   // 32B per k16 within the 128B row
        uint32_t a_r[2][4];
#pragma unroll
        for (int mt = 0; mt < 2; mt++) {
            ldsm4(a_r[mt], sb + (wm + (mt << 4) + (lane & 15)) * 144
                         + kbyte + ((lane >> 4) << 4));
        }
        const int g = lane >> 3;
#pragma unroll
        for (int p = 0; p < 4; p++) {
            uint32_t addr;
            if (!BT) {
                addr = sb + OB + (wn + (((p << 1) + (g >> 1)) << 3) + (lane & 7)) * 144
                     + kbyte + ((g & 1) << 4);
            } else {
                addr = sb + OB + ((kk << 4) + ((g & 1) << 3) + (lane & 7)) * 272
                     + ((wn + (((p << 1) + (g >> 1)) << 3)) << 1);
            }
            uint32_t r[4];
            if (!BT) ldsm4(r, addr); else ldsm4t(r, addr);
            uint32_t b0[2] = {r[0], r[1]};
            uint32_t b1[2] = {r[2], r[3]};
#pragma unroll
            for (int mt = 0; mt < 2; mt++) {
                mma16816(acc[mt][p * 2],     a_r[mt], b0);
                mma16816(acc[mt][p * 2 + 1], a_r[mt], b1);
            }
        }
    }
}

// ---------------------------------------------------------------------------
// GEMM mainloop: 128x128 CTA tile, K-chunk 64, 3-stage cp.async ring, ONE
// barrier per chunk.
// ---------------------------------------------------------------------------
template <bool BT>
__device__ __forceinline__ void gemm_run(
    float acc[2][8][4],
    const f16* __restrict__ A, size_t ap,
    const f16* __restrict__ B, size_t bp,
    int nchunks, char* sm)
{
    const int tid = threadIdx.x;
    const int lane = tid & 31, wid = tid >> 5;
    const int wm = (wid & 3) << 5;    // 0 / 32 / 64 / 96
    const int wn = (wid >> 2) << 6;   // 0 / 64
    const uint32_t sb = smem_u32(sm);

    load_stage<BT>(sb, A, ap, B, bp, 0, tid);
    if (nchunks > 1) load_stage<BT>(sb + STG, A, ap, B, bp, 1, tid);

    int s_comp = 0, s_load = 2;
    for (int ch = 0; ch < nchunks; ch++) {
        if (ch + 1 < nchunks) cpa_wait1();   // group ch complete
        else cpa_wait0();
        __syncthreads();                     // publish stage ch; ch-1 consumed
        if (ch + 2 < nchunks) {
            load_stage<BT>(sb + s_load * STG, A, ap, B, bp, ch + 2, tid);
            if (++s_load == NSTAGE) s_load = 0;
        }
        compute_chunk<BT>(acc, sb + s_comp * STG, lane, wm, wn);
        if (++s_comp == NSTAGE) s_comp = 0;
    }
}

__device__ __forceinline__ uint32_t pack2h(float v0, float v1) {
    __half2 t = __halves2half2(__float2half(v0), __float2half(v1));
    return *reinterpret_cast<uint32_t*>(&t);
}

// Shared fp16 projection epilogue (write acc tile to Y at (m0, n0)).
__device__ __forceinline__ void proj_epilogue(
    float acc[2][8][4], f16* Y, int m0, int n0)
{
    const int lane = threadIdx.x & 31, wid = threadIdx.x >> 5;
    const int wm = (wid & 3) << 5, wn = (wid >> 2) << 6;
#pragma unroll
    for (int mt = 0; mt < 2; mt++)
#pragma unroll
        for (int nt = 0; nt < 8; nt++) {
            const int col = n0 + wn + (nt << 3) + ((lane & 3) << 1);
#pragma unroll
            for (int h = 0; h < 2; h++) {
                const int row = m0 + wm + (mt << 4) + (lane >> 2) + (h << 3);
                *(uint32_t*)(Y + (size_t)row * PD + col) =
                    pack2h(acc[mt][nt][2 * h], acc[mt][nt][2 * h + 1]);
            }
        }
}

// ---------------------------------------------------------------------------
// Combined input conversion: z<3 -> W^T transpose tiles; z>=3 -> x blocks.
// ---------------------------------------------------------------------------
__global__ __launch_bounds__(256) void conv_kernel(const float* __restrict__ x,
                                                   const float* __restrict__ Wq,
                                                   const float* __restrict__ Wk,
                                                   const float* __restrict__ Wv) {
    if (blockIdx.z >= 3) {
        // ---- x -> fp16 plane ----
        const int bidx = (blockIdx.z - 3) * 1024 + blockIdx.y * 32 + blockIdx.x;
        size_t i = ((size_t)bidx * 256 + threadIdx.x) * 4;
        float4 v = *(const float4*)(x + i);
        *(uint2*)(g_x + i) = make_uint2(pack2h(v.x, v.y), pack2h(v.z, v.w));
        return;
    }
    // ---- W -> W^T fp16 plane ----
    __shared__ float t[32][33];
    const float* W = blockIdx.z == 0 ? Wq : blockIdx.z == 1 ? Wk : Wv;
    const int n0 = blockIdx.x * 32, k0 = blockIdx.y * 32;
    const int tx = threadIdx.x & 31, ty = threadIdx.x >> 5;
    for (int i = ty; i < 32; i += 8)
        t[i][tx] = W[(size_t)(k0 + i) * PD + n0 + tx];
    __syncthreads();
    const size_t base = (size_t)blockIdx.z << 20;
    for (int i = ty; i < 32; i += 8)
        g_Wt[base + (size_t)(n0 + i) * PD + k0 + tx] = __float2half(t[tx][i]);
}

// ---------------------------------------------------------------------------
// Projections Q,K only: z=0 -> Q, z=1 -> K.  CTA tile 128m x 128n.
// ---------------------------------------------------------------------------
extern __shared__ char dynsm[];

__global__ __launch_bounds__(256, 2) void proj_mma_kernel() {
    const int z = blockIdx.z;
    const int n0 = blockIdx.x << 7, m0 = blockIdx.y << 7;
    float acc[2][8][4] = {};
    const size_t ao = (size_t)m0 * PD;
    const size_t bo = ((size_t)z << 20) + (size_t)n0 * PD;
    gemm_run<false>(acc, g_x + ao, PD, g_Wt + bo, PD, 16, dynsm);
    proj_epilogue(acc, z == 0 ? g_Q : g_K, m0, n0);
}

// ---------------------------------------------------------------------------
// Scores (z<4): P' = exp(Q.K^T/32 - 5) on causal tiles, masked -> 0, plus
// per-64-col-half row partial sums into g_psum. qt reversed for scheduling.
// V-projection (z==4): fills the causal-skip bubbles and tail of this launch.
// ---------------------------------------------------------------------------
__global__ __launch_bounds__(256, 2) void scores_mma_kernel() {
    if (blockIdx.z == 4) {
        // ---- V projection tile ----
        const int idx = blockIdx.y * 32 + blockIdx.x;   // 0..1023
        const int n0 = (idx & 7) << 7, m0 = (idx >> 3) << 7;
        float acc[2][8][4] = {};
        gemm_run<false>(acc, g_x + (size_t)m0 * PD, PD,
                        g_Wt + ((size_t)2 << 20) + (size_t)n0 * PD, PD, 16, dynsm);
        proj_epilogue(acc, g_V, m0, n0);
        return;
    }
    const int kt = blockIdx.x, qt = 31 - blockIdx.y, b = blockIdx.z;
    if (kt > qt) return;
    const int q0 = qt << 7, k0 = kt << 7;
    float acc[2][8][4] = {};
    const size_t ao = (size_t)(b * PS + q0) * PD;
    const size_t bo = (size_t)(b * PS + k0) * PD;
    gemm_run<false>(acc, g_Q + ao, PD, g_K + bo, PD, 16, dynsm);

    const int lane = threadIdx.x & 31, wid = threadIdx.x >> 5;
    const int wm = (wid & 3) << 5, wn = (wid >> 2) << 6;
    f16* Pb = g_P + (size_t)b * PS * PS;
    float rsum[2][2] = {};
#pragma unroll
    for (int mt = 0; mt < 2; mt++)
#pragma unroll
        for (int nt = 0; nt < 8; nt++) {
            const int k = k0 + wn + (nt << 3) + ((lane & 3) << 1);
#pragma unroll
            for (int h = 0; h < 2; h++) {
                const int q = q0 + wm + (mt << 4) + (lane >> 2) + (h << 3);
                const float p0 = (k > q) ? 0.f
                    : __expf(acc[mt][nt][2 * h] * 0.03125f - 5.0f);
                const float p1 = (k + 1 > q) ? 0.f
                    : __expf(acc[mt][nt][2 * h + 1] * 0.03125f - 5.0f);
                *(uint32_t*)(Pb + (size_t)q * PS + k) = pack2h(p0, p1);
                rsum[mt][h] += p0 + p1;
            }
        }
    // Combine the 4 lanes holding each row (lane&3 group), write partials.
#pragma unroll
    for (int mt = 0; mt < 2; mt++)
#pragma unroll
        for (int h = 0; h < 2; h++) {
            float s = rsum[mt][h];
            s += __shfl_xor_sync(0xffffffffu, s, 1);
            s += __shfl_xor_sync(0xffffffffu, s, 2);
            if ((lane & 3) == 0) {
                const int q = q0 + wm + (mt << 4) + (lane >> 2) + (h << 3);
                g_psum[(kt << 1) + (wn >> 6)][b * PS + q] = s;
            }
        }
}

// ---------------------------------------------------------------------------
// PV: O = (P'.V) * inv_rowsum. CTA tile 128q x 128d, trans-B from [s][d].
// Row-sum finalize folded into the epilogue (coalesced psum reduce, same
// summation order as the old rsum kernel -> identical values).
// qt reversed so the heaviest (large-K) tiles schedule first.
// ---------------------------------------------------------------------------
__global__ __launch_bounds__(256, 2) void pv_mma_kernel(float* __restrict__ Out) {
    __shared__ float s_inv[128];
    const int nt0 = blockIdx.x, qt = 31 - blockIdx.y, b = blockIdx.z;
    const int q0 = qt << 7, n0 = nt0 << 7;
    float acc[2][8][4] = {};
    const size_t ao = (size_t)b * PS * PS + (size_t)q0 * PS;
    const size_t bo = (size_t)(b * PS) * PD + n0;
    gemm_run<true>(acc, g_P + ao, PS, g_V + bo, PD, (qt + 1) << 1, dynsm);

    const int tid = threadIdx.x;
    if (tid < 128) {
        const int row = b * PS + q0 + tid;
        const int nh = (qt + 1) << 1;
        float s = 0.f;
        for (int i = 0; i < nh; i++) s += g_psum[i][row];
        s_inv[tid] = 1.0f / s;
    }
    __syncthreads();

    const int lane = tid & 31, wid = tid >> 5;
    const int wm = (wid & 3) << 5, wn = (wid >> 2) << 6;
    float inv[2][2];
#pragma unroll
    for (int mt = 0; mt < 2; mt++)
#pragma unroll
        for (int h = 0; h < 2; h++)
            inv[mt][h] = s_inv[wm + (mt << 4) + (lane >> 2) + (h << 3)];

#pragma unroll
    for (int mt = 0; mt < 2; mt++)
#pragma unroll
        for (int nt = 0; nt < 8; nt++) {
            const int col = n0 + wn + (nt << 3) + ((lane & 3) << 1);
#pragma unroll
            for (int h = 0; h < 2; h++) {
                const int row = q0 + wm + (mt << 4) + (lane >> 2) + (h << 3);
                *(float2*)(Out + ((size_t)b * PS + row) * PD + col) =
                    make_float2(acc[mt][nt][2 * h] * inv[mt][h],
                                acc[mt][nt][2 * h + 1] * inv[mt][h]);
            }
        }
}

// ---------------------------------------------------------------------------
extern "C" void kernel_launch(void* const* d_in, const int* in_sizes, int n_in,
                              void* d_out, int out_size) {
    (void)in_sizes; (void)n_in; (void)out_size;
    const float* x  = (const float*)d_in[0];
    const float* Wq = (const float*)d_in[1];
    const float* Wk = (const float*)d_in[2];
    const float* Wv = (const float*)d_in[3];
    float* out = (float*)d_out;

    const int smem = NSTAGE * STG;   // 110592 B
    cudaFuncSetAttribute(proj_mma_kernel,   cudaFuncAttributeMaxDynamicSharedMemorySize, smem);
    cudaFuncSetAttribute(scores_mma_kernel, cudaFuncAttributeMaxDynamicSharedMemorySize, smem);
    cudaFuncSetAttribute(pv_mma_kernel,     cudaFuncAttributeMaxDynamicSharedMemorySize, smem);

    conv_kernel<<<dim3(32, 32, 19), 256>>>(x, Wq, Wk, Wv);   // x + W^T planes

    proj_mma_kernel<<<dim3(8, 128, 2), 256, smem>>>();       // Q, K

    scores_mma_kernel<<<dim3(32, 32, 5), 256, smem>>>();     // scores + V-proj

    pv_mma_kernel<<<dim3(8, 32, 4), 256, smem>>>(out);       // PV (+rsum fold)
}